// round 11
// baseline (speedup 1.0000x reference)
#include <cuda_runtime.h>

// ---------------- problem constants ----------------
static constexpr int H   = 128;
static constexpr int NUc = 200000;
static constexpr int NMc = 80000;
static constexpr int FDc = 512;

// ---------------- scratch (device globals; no allocation allowed) ----------------
__device__ __align__(128) float g_movie_x[(size_t)NMc * H];
__device__ __align__(128) float g_t      [(size_t)NMc * H];
__device__ __align__(128) float g_movie_h[(size_t)NMc * H];
__device__ __align__(128) float g_aggM   [(size_t)NMc * H];
__device__ __align__(128) float g_user_h [(size_t)NUc * H];
__device__ __align__(128) float g_aggU   [(size_t)NUc * H];
__device__ __align__(128) int   g_deg_u[NUc];
__device__ __align__(128) int   g_deg_m[NMc];
__device__ __align__(128) float g_u1 [H];   // user_init @ Wl1_um
__device__ __align__(128) float g_cU1[H];   // bl1_mu + user_init @ Wr1_mu

// ---------------- utility kernels ----------------
__global__ void zero_f4(float* __restrict__ p, int n4) {
    int i = blockIdx.x * blockDim.x + threadIdx.x;
    if (i < n4) reinterpret_cast<float4*>(p)[i] = make_float4(0.f, 0.f, 0.f, 0.f);
}

__global__ void zero_int(int* __restrict__ p, int n) {
    int i = blockIdx.x * blockDim.x + threadIdx.x;
    if (i < n) p[i] = 0;
}

__global__ void degrees_kernel(const int* __restrict__ es, const int* __restrict__ ed,
                               int* __restrict__ deg_u, int* __restrict__ deg_m, int E) {
    int i = blockIdx.x * blockDim.x + threadIdx.x;
    if (i < E) {
        atomicAdd(&deg_u[es[i]], 1);
        atomicAdd(&deg_m[ed[i]], 1);
    }
}

// u1 = user_init @ Wl1_um ; cU1 = bl1_mu + user_init @ Wr1_mu
__global__ void precompute_kernel(const float* __restrict__ uinit,
                                  const float* __restrict__ Wl1_um,
                                  const float* __restrict__ bl1_mu,
                                  const float* __restrict__ Wr1_mu) {
    int j = threadIdx.x;  // 0..127
    float s1 = 0.f, s2 = 0.f;
    for (int i = 0; i < H; i++) {
        float u = uinit[i];
        s1 = fmaf(u, Wl1_um[i * H + j], s1);
        s2 = fmaf(u, Wr1_mu[i * H + j], s2);
    }
    g_u1[j]  = s1;
    g_cU1[j] = bl1_mu[j] + s2;
}

// ---------------- GEMM: C[M,128] = A[M,K] @ W[K,128] (+epilogue) ----------------
// mode 0: C = acc + bias(optional)
// mode 1: C = relu(acc + bias + (deg[row]>0 ? u1 : 0))              (movie_h)
// mode 2: C = acc + bias + C_prev * (1/max(deg[row],1))             (user_o, in place over aggU)
// mode 3: C = acc * (1/max(deg[row],1)) + bias                      (movie_o part 1: mean @ W)
// mode 4: C = C_prev + acc                                          (movie_o part 2 accumulate)
__global__ __launch_bounds__(256) void gemm128(
    const float* __restrict__ A, const float* __restrict__ W,
    float* __restrict__ C, int M, int K,
    const float* __restrict__ bias,
    const float* __restrict__ u1,
    const int* __restrict__ deg,
    int mode)
{
    __shared__ float As[32][64];
    __shared__ float Ws[32][128];
    const int tid  = threadIdx.x;
    const int lane = tid & 31;
    const int wid  = tid >> 5;
    const int row0 = blockIdx.x * 64;

    float acc[8][4];
#pragma unroll
    for (int i = 0; i < 8; i++) { acc[i][0] = 0.f; acc[i][1] = 0.f; acc[i][2] = 0.f; acc[i][3] = 0.f; }

    for (int k0 = 0; k0 < K; k0 += 32) {
        // A tile 64x32 (transposed into As[k][m]) -- 512 float4 / 256 threads
#pragma unroll
        for (int l = 0; l < 2; l++) {
            int idx = tid + l * 256;
            int r   = idx >> 3;      // 0..63
            int c4  = idx & 7;       // float4 within row
            int grow = row0 + r;
            float4 v = make_float4(0.f, 0.f, 0.f, 0.f);
            if (grow < M) v = *reinterpret_cast<const float4*>(A + (size_t)grow * K + k0 + c4 * 4);
            As[c4 * 4 + 0][r] = v.x;
            As[c4 * 4 + 1][r] = v.y;
            As[c4 * 4 + 2][r] = v.z;
            As[c4 * 4 + 3][r] = v.w;
        }
        // W tile 32x128 -- 1024 float4 / 256 threads
#pragma unroll
        for (int l = 0; l < 4; l++) {
            int idx = tid + l * 256;
            int r   = idx >> 5;      // 0..31
            int c   = idx & 31;      // float4 within row
            *reinterpret_cast<float4*>(&Ws[r][c * 4]) =
                *reinterpret_cast<const float4*>(W + (size_t)(k0 + r) * H + c * 4);
        }
        __syncthreads();
#pragma unroll
        for (int k = 0; k < 32; k++) {
            float4 wv = *reinterpret_cast<const float4*>(&Ws[k][lane * 4]);
            float4 a0 = *reinterpret_cast<const float4*>(&As[k][wid * 8]);
            float4 a1 = *reinterpret_cast<const float4*>(&As[k][wid * 8 + 4]);
            float ar[8] = {a0.x, a0.y, a0.z, a0.w, a1.x, a1.y, a1.z, a1.w};
#pragma unroll
            for (int i = 0; i < 8; i++) {
                acc[i][0] = fmaf(ar[i], wv.x, acc[i][0]);
                acc[i][1] = fmaf(ar[i], wv.y, acc[i][1]);
                acc[i][2] = fmaf(ar[i], wv.z, acc[i][2]);
                acc[i][3] = fmaf(ar[i], wv.w, acc[i][3]);
            }
        }
        __syncthreads();
    }

    const int col = lane * 4;
    float4 bv = make_float4(0.f, 0.f, 0.f, 0.f);
    if (bias) bv = *reinterpret_cast<const float4*>(bias + col);
    float4 uv = make_float4(0.f, 0.f, 0.f, 0.f);
    if (u1)   uv = *reinterpret_cast<const float4*>(u1 + col);

#pragma unroll
    for (int i = 0; i < 8; i++) {
        int grow = row0 + wid * 8 + i;
        if (grow >= M) continue;
        float* cp = C + (size_t)grow * H + col;
        float4 o = make_float4(acc[i][0] + bv.x, acc[i][1] + bv.y,
                               acc[i][2] + bv.z, acc[i][3] + bv.w);
        if (mode == 1) {
            if (deg[grow] > 0) { o.x += uv.x; o.y += uv.y; o.z += uv.z; o.w += uv.w; }
            o.x = fmaxf(o.x, 0.f); o.y = fmaxf(o.y, 0.f);
            o.z = fmaxf(o.z, 0.f); o.w = fmaxf(o.w, 0.f);
        } else if (mode == 2) {
            float inv = 1.f / (float)max(deg[grow], 1);
            float4 p = *reinterpret_cast<const float4*>(cp);
            o.x += p.x * inv; o.y += p.y * inv; o.z += p.z * inv; o.w += p.w * inv;
        } else if (mode == 3) {
            float inv = 1.f / (float)max(deg[grow], 1);
            o.x = acc[i][0] * inv + bv.x; o.y = acc[i][1] * inv + bv.y;
            o.z = acc[i][2] * inv + bv.z; o.w = acc[i][3] * inv + bv.w;
        } else if (mode == 4) {
            float4 p = *reinterpret_cast<const float4*>(cp);
            o.x += p.x; o.y += p.y; o.z += p.z; o.w += p.w;
        }
        *reinterpret_cast<float4*>(cp) = o;
    }
}

// ---------------- edge scatter: agg[sidx[e]] += feat[gidx[e]] (one warp / edge) ----------------
__device__ __forceinline__ void atomic_add_f4(float4* addr, float4 v) {
#if __CUDA_ARCH__ >= 900
    atomicAdd(addr, v);
#else
    float* f = reinterpret_cast<float*>(addr);
    atomicAdd(f + 0, v.x); atomicAdd(f + 1, v.y);
    atomicAdd(f + 2, v.z); atomicAdd(f + 3, v.w);
#endif
}

__global__ __launch_bounds__(256) void edge_scatter(
    const float* __restrict__ feat,
    const int* __restrict__ gidx, const int* __restrict__ sidx,
    float* __restrict__ agg, int E)
{
    int w = (blockIdx.x * blockDim.x + threadIdx.x) >> 5;
    int lane = threadIdx.x & 31;
    if (w >= E) return;
    int g = gidx[w];
    int s = sidx[w];
    float4 v = *reinterpret_cast<const float4*>(feat + (size_t)g * H + lane * 4);
    atomic_add_f4(reinterpret_cast<float4*>(agg + (size_t)s * H + lane * 4), v);
}

// ---------------- user_h = relu(aggU / max(deg,1) + cU1) ----------------
__global__ void finish_user_h(float* __restrict__ uh, const float* __restrict__ agg,
                              const int* __restrict__ deg, int nU)
{
    int i = blockIdx.x * blockDim.x + threadIdx.x;  // over nU*32 float4s
    if (i >= nU * 32) return;
    int row = i >> 5;
    int c4  = i & 31;
    float inv = 1.f / (float)max(deg[row], 1);
    float4 v = reinterpret_cast<const float4*>(agg)[i];
    float4 c = *reinterpret_cast<const float4*>(g_cU1 + c4 * 4);
    float4 o;
    o.x = fmaxf(fmaf(v.x, inv, c.x), 0.f);
    o.y = fmaxf(fmaf(v.y, inv, c.y), 0.f);
    o.z = fmaxf(fmaf(v.z, inv, c.z), 0.f);
    o.w = fmaxf(fmaf(v.w, inv, c.w), 0.f);
    reinterpret_cast<float4*>(uh)[i] = o;
}

// ---------------- out[e] = dot(user_o[lu[e]], movie_o[lm[e]]) ----------------
__global__ __launch_bounds__(256) void edge_dot(
    const float* __restrict__ uo, const float* __restrict__ mo,
    const int* __restrict__ lu, const int* __restrict__ lm,
    float* __restrict__ out, int EL)
{
    int w = (blockIdx.x * blockDim.x + threadIdx.x) >> 5;
    int lane = threadIdx.x & 31;
    if (w >= EL) return;
    float4 a = *reinterpret_cast<const float4*>(uo + (size_t)lu[w] * H + lane * 4);
    float4 b = *reinterpret_cast<const float4*>(mo + (size_t)lm[w] * H + lane * 4);
    float d = a.x * b.x + a.y * b.y + a.z * b.z + a.w * b.w;
#pragma unroll
    for (int off = 16; off; off >>= 1) d += __shfl_xor_sync(0xffffffffu, d, off);
    if (lane == 0) out[w] = d;
}

// ---------------- launcher ----------------
extern "C" void kernel_launch(void* const* d_in, const int* in_sizes, int n_in,
                              void* d_out, int out_size)
{
    const float* movie_feats = (const float*)d_in[0];
    const float* user_init   = (const float*)d_in[1];
    const int*   edge_src    = (const int*)d_in[2];
    const int*   edge_dst    = (const int*)d_in[3];
    const int*   lbl_user    = (const int*)d_in[4];
    const int*   lbl_movie   = (const int*)d_in[5];
    // d_in[6] = n_users (scalar) if present; weights follow
    const int base = (n_in >= 21) ? 7 : 6;
    const float* Wm     = (const float*)d_in[base + 0];
    const float* bm     = (const float*)d_in[base + 1];
    const float* Wl1_um = (const float*)d_in[base + 2];
    const float* bl1_um = (const float*)d_in[base + 3];
    const float* Wr1_um = (const float*)d_in[base + 4];
    const float* Wl1_mu = (const float*)d_in[base + 5];
    const float* bl1_mu = (const float*)d_in[base + 6];
    const float* Wr1_mu = (const float*)d_in[base + 7];
    const float* Wl2_um = (const float*)d_in[base + 8];
    const float* bl2_um = (const float*)d_in[base + 9];
    const float* Wr2_um = (const float*)d_in[base + 10];
    const float* Wl2_mu = (const float*)d_in[base + 11];
    const float* bl2_mu = (const float*)d_in[base + 12];
    const float* Wr2_mu = (const float*)d_in[base + 13];

    const int E  = in_sizes[2];
    const int EL = in_sizes[4];
    const int nm = in_sizes[0] / FDc;   // 80000
    const int nu = NUc;                 // 200000

    // device-global scratch addresses
    void *p_mx, *p_t, *p_mh, *p_aM, *p_uh, *p_aU, *p_du, *p_dm, *p_u1;
    cudaGetSymbolAddress(&p_mx, g_movie_x);
    cudaGetSymbolAddress(&p_t,  g_t);
    cudaGetSymbolAddress(&p_mh, g_movie_h);
    cudaGetSymbolAddress(&p_aM, g_aggM);
    cudaGetSymbolAddress(&p_uh, g_user_h);
    cudaGetSymbolAddress(&p_aU, g_aggU);
    cudaGetSymbolAddress(&p_du, g_deg_u);
    cudaGetSymbolAddress(&p_dm, g_deg_m);
    cudaGetSymbolAddress(&p_u1, g_u1);

    float* mx = (float*)p_mx;  float* t  = (float*)p_t;
    float* mh = (float*)p_mh;  float* aM = (float*)p_aM;
    float* uh = (float*)p_uh;  float* aU = (float*)p_aU;
    int* du = (int*)p_du;      int* dm = (int*)p_dm;
    float* u1 = (float*)p_u1;
    float* out = (float*)d_out;

    const int TB = 256;
    const int nu4 = nu * 32, nm4 = nm * 32;

    // zero accumulators + degrees
    zero_f4<<<(nu4 + TB - 1) / TB, TB>>>(aU, nu4);
    zero_f4<<<(nm4 + TB - 1) / TB, TB>>>(aM, nm4);
    zero_int<<<(nu + TB - 1) / TB, TB>>>(du, nu);
    zero_int<<<(nm + TB - 1) / TB, TB>>>(dm, nm);
    degrees_kernel<<<(E + TB - 1) / TB, TB>>>(edge_src, edge_dst, du, dm, E);
    precompute_kernel<<<1, H>>>(user_init, Wl1_um, bl1_mu, Wr1_mu);

    // movie_x = movie_feats @ Wm + bm
    gemm128<<<(nm + 63) / 64, TB>>>(movie_feats, Wm, mx, nm, FDc, bm, nullptr, nullptr, 0);

    // conv1: t1 = movie_x @ Wl1_mu ; scatter-mean into users ; user_h = relu(...)
    gemm128<<<(nm + 63) / 64, TB>>>(mx, Wl1_mu, t, nm, H, nullptr, nullptr, nullptr, 0);
    edge_scatter<<<(E + 7) / 8, TB>>>(t, edge_dst, edge_src, aU, E);
    finish_user_h<<<(nu4 + TB - 1) / TB, TB>>>(uh, aU, du, nu);

    // conv1: movie_h = relu(movie_x @ Wr1_um + bl1_um + (deg_m>0)*u1)
    gemm128<<<(nm + 63) / 64, TB>>>(mx, Wr1_um, mh, nm, H, bl1_um, u1, dm, 1);

    // conv2 user side: t2 = movie_h @ Wl2_mu ; scatter into aggU (re-zeroed)
    gemm128<<<(nm + 63) / 64, TB>>>(mh, Wl2_mu, t, nm, H, nullptr, nullptr, nullptr, 0);
    zero_f4<<<(nu4 + TB - 1) / TB, TB>>>(aU, nu4);
    edge_scatter<<<(E + 7) / 8, TB>>>(t, edge_dst, edge_src, aU, E);
    // user_o (written in-place into aggU) = user_h @ Wr2_mu + bl2_mu + aggU/deg
    gemm128<<<(nu + 63) / 64, TB>>>(uh, Wr2_mu, aU, nu, H, bl2_mu, nullptr, du, 2);

    // conv2 movie side: aggregate user_h into movies, then transform
    edge_scatter<<<(E + 7) / 8, TB>>>(uh, edge_src, edge_dst, aM, E);
    // movie_o (into g_movie_x, reused) = (aggM/deg) @ Wl2_um + bl2_um  ...
    gemm128<<<(nm + 63) / 64, TB>>>(aM, Wl2_um, mx, nm, H, bl2_um, nullptr, dm, 3);
    // ... += movie_h @ Wr2_um
    gemm128<<<(nm + 63) / 64, TB>>>(mh, Wr2_um, mx, nm, H, nullptr, nullptr, nullptr, 4);

    // supervision-edge dot products
    edge_dot<<<(EL + 7) / 8, TB>>>(aU, mx, lbl_user, lbl_movie, out, EL);
}

// round 12
// speedup vs baseline: 1.2402x; 1.2402x over previous
#include <cuda_runtime.h>
#include <cstdint>

// ---------------- problem constants ----------------
static constexpr int H   = 128;
static constexpr int NUc = 200000;
static constexpr int NMc = 80000;
static constexpr int FDc = 512;

// ---------------- scratch (device globals; no allocation allowed) ----------------
__device__ __align__(128) float g_movie_x[(size_t)NMc * H];
__device__ __align__(128) float g_t      [(size_t)NMc * H];
__device__ __align__(128) float g_movie_h[(size_t)NMc * H];
__device__ __align__(128) float g_aggM   [(size_t)NMc * H];
__device__ __align__(128) float g_user_h [(size_t)NUc * H];
__device__ __align__(128) float g_aggU   [(size_t)NUc * H];
__device__ __align__(128) int   g_deg_u[NUc];
__device__ __align__(128) int   g_deg_m[NMc];
__device__ __align__(128) float g_u1 [H];   // user_init @ Wl1_um
__device__ __align__(128) float g_cU1[H];   // bl1_mu + user_init @ Wr1_mu

// ---------------- utility kernels ----------------
__global__ void zero_f4(float* __restrict__ p, int n4) {
    int i = blockIdx.x * blockDim.x + threadIdx.x;
    if (i < n4) reinterpret_cast<float4*>(p)[i] = make_float4(0.f, 0.f, 0.f, 0.f);
}

__global__ void zero_int(int* __restrict__ p, int n) {
    int i = blockIdx.x * blockDim.x + threadIdx.x;
    if (i < n) p[i] = 0;
}

__global__ void degrees_kernel(const int* __restrict__ es, const int* __restrict__ ed,
                               int* __restrict__ deg_u, int* __restrict__ deg_m, int E) {
    int i = blockIdx.x * blockDim.x + threadIdx.x;
    if (i < E) {
        atomicAdd(&deg_u[es[i]], 1);
        atomicAdd(&deg_m[ed[i]], 1);
    }
}

// u1 = user_init @ Wl1_um ; cU1 = bl1_mu + user_init @ Wr1_mu
__global__ void precompute_kernel(const float* __restrict__ uinit,
                                  const float* __restrict__ Wl1_um,
                                  const float* __restrict__ bl1_mu,
                                  const float* __restrict__ Wr1_mu) {
    int j = threadIdx.x;  // 0..127
    float s1 = 0.f, s2 = 0.f;
    for (int i = 0; i < H; i++) {
        float u = uinit[i];
        s1 = fmaf(u, Wl1_um[i * H + j], s1);
        s2 = fmaf(u, Wr1_mu[i * H + j], s2);
    }
    g_u1[j]  = s1;
    g_cU1[j] = bl1_mu[j] + s2;
}

// ---------------- tf32 helpers ----------------
__device__ __forceinline__ uint32_t f2tf32(float f) {
    uint32_t o;
    asm("cvt.rna.tf32.f32 %0, %1;" : "=r"(o) : "f"(f));
    return o;
}

__device__ __forceinline__ void mma_tf32(float c[4], const uint32_t a[4], const uint32_t b[2]) {
    asm volatile(
        "mma.sync.aligned.m16n8k8.row.col.f32.tf32.tf32.f32 "
        "{%0,%1,%2,%3}, {%4,%5,%6,%7}, {%8,%9}, {%0,%1,%2,%3};"
        : "+f"(c[0]), "+f"(c[1]), "+f"(c[2]), "+f"(c[3])
        : "r"(a[0]), "r"(a[1]), "r"(a[2]), "r"(a[3]), "r"(b[0]), "r"(b[1]));
}

// ---------------- tensor-core GEMM: C[M,128] = A[M,K] @ W[K,128] (+epilogue) ----------------
// Block tile 128x128, 8 warps (4 along M x 2 along N), warp tile 32x64.
// K-tile 32 (4 k8 steps of m16n8k8 tf32 mma).
// mode 0: C = acc + bias(optional)
// mode 1: C = relu(acc + bias + (deg[row]>0 ? u1 : 0))
// mode 2: C = acc + bias + C_prev * (1/max(deg[row],1))
// mode 3: C = acc * (1/max(deg[row],1)) + bias
// mode 4: C = C_prev + acc
__global__ __launch_bounds__(256) void gemm_tc(
    const float* __restrict__ A, const float* __restrict__ W,
    float* __restrict__ C, int M, int K,
    const float* __restrict__ bias,
    const float* __restrict__ u1,
    const int* __restrict__ deg,
    int mode)
{
    // A tile: [128 rows][32 k], row stride 36 -> bank (4m+k)%32 conflict-free frag loads
    __shared__ uint32_t As[128 * 36];
    // W tile: [32 k][128 n], row stride 136 -> bank (8k+n)%32 conflict-free frag loads
    __shared__ uint32_t Ws[32 * 136];

    const int tid   = threadIdx.x;
    const int lane  = tid & 31;
    const int wid   = tid >> 5;
    const int warpM = wid >> 1;          // 0..3
    const int warpN = wid & 1;           // 0..1
    const int row0  = blockIdx.x * 128;

    float acc[2][8][4];
#pragma unroll
    for (int mb = 0; mb < 2; mb++)
#pragma unroll
        for (int nb = 0; nb < 8; nb++) {
            acc[mb][nb][0] = 0.f; acc[mb][nb][1] = 0.f;
            acc[mb][nb][2] = 0.f; acc[mb][nb][3] = 0.f;
        }

    for (int k0 = 0; k0 < K; k0 += 32) {
        // ---- load A tile (128x32 fp32 = 1024 float4 over 256 threads) ----
#pragma unroll
        for (int l = 0; l < 4; l++) {
            int idx  = tid + l * 256;
            int r    = idx >> 3;          // 0..127
            int c4   = idx & 7;           // float4 within the 32-wide row
            int grow = row0 + r;
            float4 v = make_float4(0.f, 0.f, 0.f, 0.f);
            if (grow < M) v = *reinterpret_cast<const float4*>(A + (size_t)grow * K + k0 + c4 * 4);
            uint4 t;
            t.x = f2tf32(v.x); t.y = f2tf32(v.y); t.z = f2tf32(v.z); t.w = f2tf32(v.w);
            *reinterpret_cast<uint4*>(&As[r * 36 + c4 * 4]) = t;   // 144B row stride, 16B aligned
        }
        // ---- load W tile (32x128 fp32 = 1024 float4 over 256 threads) ----
#pragma unroll
        for (int l = 0; l < 4; l++) {
            int idx = tid + l * 256;
            int r   = idx >> 5;           // 0..31
            int c   = idx & 31;           // float4 within the 128-wide row
            float4 v = *reinterpret_cast<const float4*>(W + (size_t)(k0 + r) * H + c * 4);
            uint4 t;
            t.x = f2tf32(v.x); t.y = f2tf32(v.y); t.z = f2tf32(v.z); t.w = f2tf32(v.w);
            *reinterpret_cast<uint4*>(&Ws[r * 136 + c * 4]) = t;   // 544B row stride, 16B aligned
        }
        __syncthreads();

#pragma unroll
        for (int s = 0; s < 4; s++) {
            const int ka = s * 8 + (lane & 3);
            uint32_t a[2][4];
#pragma unroll
            for (int mb = 0; mb < 2; mb++) {
                int mA = warpM * 32 + mb * 16 + (lane >> 2);
                a[mb][0] = As[mA * 36 + ka];
                a[mb][1] = As[(mA + 8) * 36 + ka];
                a[mb][2] = As[mA * 36 + ka + 4];
                a[mb][3] = As[(mA + 8) * 36 + ka + 4];
            }
            uint32_t b[8][2];
            const int nB = warpN * 64 + (lane >> 2);
#pragma unroll
            for (int nb = 0; nb < 8; nb++) {
                b[nb][0] = Ws[ka * 136 + nB + nb * 8];
                b[nb][1] = Ws[(ka + 4) * 136 + nB + nb * 8];
            }
#pragma unroll
            for (int mb = 0; mb < 2; mb++)
#pragma unroll
                for (int nb = 0; nb < 8; nb++)
                    mma_tf32(acc[mb][nb], a[mb], b[nb]);
        }
        __syncthreads();
    }

    // ---------------- epilogue ----------------
    const int col0 = warpN * 64 + (lane & 3) * 2;

#pragma unroll
    for (int mb = 0; mb < 2; mb++) {
        int rA = row0 + warpM * 32 + mb * 16 + (lane >> 2);
        int rB = rA + 8;
        float invA = 1.f, invB = 1.f;
        int   dA = 0,    dB = 0;
        if (deg) {
            if (rA < M) { dA = deg[rA]; invA = 1.f / (float)max(dA, 1); }
            if (rB < M) { dB = deg[rB]; invB = 1.f / (float)max(dB, 1); }
        }
#pragma unroll
        for (int nb = 0; nb < 8; nb++) {
            int n = col0 + nb * 8;
            float bx = 0.f, by = 0.f;
            if (bias) { bx = bias[n]; by = bias[n + 1]; }
            float c0 = acc[mb][nb][0], c1 = acc[mb][nb][1];
            float c2 = acc[mb][nb][2], c3 = acc[mb][nb][3];

            // row rA -> (c0, c1)
            if (rA < M) {
                float* cp = C + (size_t)rA * H + n;
                float ox, oy;
                if (mode == 0) {
                    ox = c0 + bx; oy = c1 + by;
                } else if (mode == 1) {
                    ox = c0 + bx; oy = c1 + by;
                    if (dA > 0) { ox += u1[n]; oy += u1[n + 1]; }
                    ox = fmaxf(ox, 0.f); oy = fmaxf(oy, 0.f);
                } else if (mode == 2) {
                    float2 p = *reinterpret_cast<const float2*>(cp);
                    ox = c0 + bx + p.x * invA; oy = c1 + by + p.y * invA;
                } else if (mode == 3) {
                    ox = c0 * invA + bx; oy = c1 * invA + by;
                } else { // mode 4
                    float2 p = *reinterpret_cast<const float2*>(cp);
                    ox = p.x + c0; oy = p.y + c1;
                }
                *reinterpret_cast<float2*>(cp) = make_float2(ox, oy);
            }
            // row rB -> (c2, c3)
            if (rB < M) {
                float* cp = C + (size_t)rB * H + n;
                float ox, oy;
                if (mode == 0) {
                    ox = c2 + bx; oy = c3 + by;
                } else if (mode == 1) {
                    ox = c2 + bx; oy = c3 + by;
                    if (dB > 0) { ox += u1[n]; oy += u1[n + 1]; }
                    ox = fmaxf(ox, 0.f); oy = fmaxf(oy, 0.f);
                } else if (mode == 2) {
                    float2 p = *reinterpret_cast<const float2*>(cp);
                    ox = c2 + bx + p.x * invB; oy = c3 + by + p.y * invB;
                } else if (mode == 3) {
                    ox = c2 * invB + bx; oy = c3 * invB + by;
                } else { // mode 4
                    float2 p = *reinterpret_cast<const float2*>(cp);
                    ox = p.x + c2; oy = p.y + c3;
                }
                *reinterpret_cast<float2*>(cp) = make_float2(ox, oy);
            }
        }
    }
}

// ---------------- edge scatter: agg[sidx[e]] += feat[gidx[e]] (one warp / edge) ----------------
__device__ __forceinline__ void atomic_add_f4(float4* addr, float4 v) {
#if __CUDA_ARCH__ >= 900
    atomicAdd(addr, v);
#else
    float* f = reinterpret_cast<float*>(addr);
    atomicAdd(f + 0, v.x); atomicAdd(f + 1, v.y);
    atomicAdd(f + 2, v.z); atomicAdd(f + 3, v.w);
#endif
}

__global__ __launch_bounds__(256) void edge_scatter(
    const float* __restrict__ feat,
    const int* __restrict__ gidx, const int* __restrict__ sidx,
    float* __restrict__ agg, int E)
{
    int w = (blockIdx.x * blockDim.x + threadIdx.x) >> 5;
    int lane = threadIdx.x & 31;
    if (w >= E) return;
    int g = gidx[w];
    int s = sidx[w];
    float4 v = *reinterpret_cast<const float4*>(feat + (size_t)g * H + lane * 4);
    atomic_add_f4(reinterpret_cast<float4*>(agg + (size_t)s * H + lane * 4), v);
}

// ---------------- user_h = relu(aggU / max(deg,1) + cU1) ----------------
__global__ void finish_user_h(float* __restrict__ uh, const float* __restrict__ agg,
                              const int* __restrict__ deg, int nU)
{
    int i = blockIdx.x * blockDim.x + threadIdx.x;  // over nU*32 float4s
    if (i >= nU * 32) return;
    int row = i >> 5;
    int c4  = i & 31;
    float inv = 1.f / (float)max(deg[row], 1);
    float4 v = reinterpret_cast<const float4*>(agg)[i];
    float4 c = *reinterpret_cast<const float4*>(g_cU1 + c4 * 4);
    float4 o;
    o.x = fmaxf(fmaf(v.x, inv, c.x), 0.f);
    o.y = fmaxf(fmaf(v.y, inv, c.y), 0.f);
    o.z = fmaxf(fmaf(v.z, inv, c.z), 0.f);
    o.w = fmaxf(fmaf(v.w, inv, c.w), 0.f);
    reinterpret_cast<float4*>(uh)[i] = o;
}

// ---------------- out[e] = dot(user_o[lu[e]], movie_o[lm[e]]) ----------------
__global__ __launch_bounds__(256) void edge_dot(
    const float* __restrict__ uo, const float* __restrict__ mo,
    const int* __restrict__ lu, const int* __restrict__ lm,
    float* __restrict__ out, int EL)
{
    int w = (blockIdx.x * blockDim.x + threadIdx.x) >> 5;
    int lane = threadIdx.x & 31;
    if (w >= EL) return;
    float4 a = *reinterpret_cast<const float4*>(uo + (size_t)lu[w] * H + lane * 4);
    float4 b = *reinterpret_cast<const float4*>(mo + (size_t)lm[w] * H + lane * 4);
    float d = a.x * b.x + a.y * b.y + a.z * b.z + a.w * b.w;
#pragma unroll
    for (int off = 16; off; off >>= 1) d += __shfl_xor_sync(0xffffffffu, d, off);
    if (lane == 0) out[w] = d;
}

// ---------------- launcher ----------------
extern "C" void kernel_launch(void* const* d_in, const int* in_sizes, int n_in,
                              void* d_out, int out_size)
{
    const float* movie_feats = (const float*)d_in[0];
    const float* user_init   = (const float*)d_in[1];
    const int*   edge_src    = (const int*)d_in[2];
    const int*   edge_dst    = (const int*)d_in[3];
    const int*   lbl_user    = (const int*)d_in[4];
    const int*   lbl_movie   = (const int*)d_in[5];
    const int base = (n_in >= 21) ? 7 : 6;
    const float* Wm     = (const float*)d_in[base + 0];
    const float* bm     = (const float*)d_in[base + 1];
    const float* Wl1_um = (const float*)d_in[base + 2];
    const float* bl1_um = (const float*)d_in[base + 3];
    const float* Wr1_um = (const float*)d_in[base + 4];
    const float* Wl1_mu = (const float*)d_in[base + 5];
    const float* bl1_mu = (const float*)d_in[base + 6];
    const float* Wr1_mu = (const float*)d_in[base + 7];
    const float* Wl2_um = (const float*)d_in[base + 8];
    const float* bl2_um = (const float*)d_in[base + 9];
    const float* Wr2_um = (const float*)d_in[base + 10];
    const float* Wl2_mu = (const float*)d_in[base + 11];
    const float* bl2_mu = (const float*)d_in[base + 12];
    const float* Wr2_mu = (const float*)d_in[base + 13];

    const int E  = in_sizes[2];
    const int EL = in_sizes[4];
    const int nm = in_sizes[0] / FDc;   // 80000
    const int nu = NUc;                 // 200000

    void *p_mx, *p_t, *p_mh, *p_aM, *p_uh, *p_aU, *p_du, *p_dm, *p_u1;
    cudaGetSymbolAddress(&p_mx, g_movie_x);
    cudaGetSymbolAddress(&p_t,  g_t);
    cudaGetSymbolAddress(&p_mh, g_movie_h);
    cudaGetSymbolAddress(&p_aM, g_aggM);
    cudaGetSymbolAddress(&p_uh, g_user_h);
    cudaGetSymbolAddress(&p_aU, g_aggU);
    cudaGetSymbolAddress(&p_du, g_deg_u);
    cudaGetSymbolAddress(&p_dm, g_deg_m);
    cudaGetSymbolAddress(&p_u1, g_u1);

    float* mx = (float*)p_mx;  float* t  = (float*)p_t;
    float* mh = (float*)p_mh;  float* aM = (float*)p_aM;
    float* uh = (float*)p_uh;  float* aU = (float*)p_aU;
    int* du = (int*)p_du;      int* dm = (int*)p_dm;
    float* u1 = (float*)p_u1;
    float* out = (float*)d_out;

    const int TB = 256;
    const int nu4 = nu * 32, nm4 = nm * 32;
    const int gNM = (nm + 127) / 128;
    const int gNU = (nu + 127) / 128;

    // zero accumulators + degrees
    zero_f4<<<(nu4 + TB - 1) / TB, TB>>>(aU, nu4);
    zero_f4<<<(nm4 + TB - 1) / TB, TB>>>(aM, nm4);
    zero_int<<<(nu + TB - 1) / TB, TB>>>(du, nu);
    zero_int<<<(nm + TB - 1) / TB, TB>>>(dm, nm);
    degrees_kernel<<<(E + TB - 1) / TB, TB>>>(edge_src, edge_dst, du, dm, E);
    precompute_kernel<<<1, H>>>(user_init, Wl1_um, bl1_mu, Wr1_mu);

    // movie_x = movie_feats @ Wm + bm
    gemm_tc<<<gNM, TB>>>(movie_feats, Wm, mx, nm, FDc, bm, nullptr, nullptr, 0);

    // conv1: t1 = movie_x @ Wl1_mu ; scatter-mean into users ; user_h = relu(...)
    gemm_tc<<<gNM, TB>>>(mx, Wl1_mu, t, nm, H, nullptr, nullptr, nullptr, 0);
    edge_scatter<<<(E + 7) / 8, TB>>>(t, edge_dst, edge_src, aU, E);
    finish_user_h<<<(nu4 + TB - 1) / TB, TB>>>(uh, aU, du, nu);

    // conv1: movie_h = relu(movie_x @ Wr1_um + bl1_um + (deg_m>0)*u1)
    gemm_tc<<<gNM, TB>>>(mx, Wr1_um, mh, nm, H, bl1_um, u1, dm, 1);

    // conv2 user side: t2 = movie_h @ Wl2_mu ; scatter into aggU (re-zeroed)
    gemm_tc<<<gNM, TB>>>(mh, Wl2_mu, t, nm, H, nullptr, nullptr, nullptr, 0);
    zero_f4<<<(nu4 + TB - 1) / TB, TB>>>(aU, nu4);
    edge_scatter<<<(E + 7) / 8, TB>>>(t, edge_dst, edge_src, aU, E);
    // user_o (in place over aggU) = user_h @ Wr2_mu + bl2_mu + aggU/deg
    gemm_tc<<<gNU, TB>>>(uh, Wr2_mu, aU, nu, H, bl2_mu, nullptr, du, 2);

    // conv2 movie side: aggregate user_h into movies, then transform
    edge_scatter<<<(E + 7) / 8, TB>>>(uh, edge_src, edge_dst, aM, E);
    // movie_o (into g_movie_x, reused) = (aggM/deg) @ Wl2_um + bl2_um ...
    gemm_tc<<<gNM, TB>>>(aM, Wl2_um, mx, nm, H, bl2_um, nullptr, dm, 3);
    // ... += movie_h @ Wr2_um
    gemm_tc<<<gNM, TB>>>(mh, Wr2_um, mx, nm, H, nullptr, nullptr, nullptr, 4);

    // supervision-edge dot products
    edge_dot<<<(EL + 7) / 8, TB>>>(aU, mx, lbl_user, lbl_movie, out, EL);
}